// round 14
// baseline (speedup 1.0000x reference)
#include <cuda_runtime.h>
#include <math.h>

// Dynamics_79843442033036 — fused analytic grad/HVV kernel.
// Round 14: occupancy push — 3 groups x 256 threads (24 warps/SM, 6/SMSP),
// TBS=16, one shared W1, pitch-20 activation rows. Same algebra as r13.

typedef unsigned long long ull;

#define HID     128
#define DIMV    8
#define BATCHN  65536
#define TBS     16
#define NTILES  (BATCHN / TBS)      // 4096
#define NTHREADS 768
#define GTHREADS 256
#define GRID    152
#define NWORKERS (GRID * 3)         // 456

#define W1P 132
#define TP  20                       // activation row pitch (floats)
#define XP  17
#define W0P 10
#define GBP 9
#define HVPP 20

// ---- shared weights (float offsets) ----
#define SM_W1   0                            // [128][132]
#define SM_W0   (SM_W1 + HID*W1P)            // 16896
#define SM_W0D  (SM_W0 + HID*W0P)            // 18176
#define SM_B0   (SM_W0D + HID*DIMV*2)        // 20224
#define SM_B1   (SM_B0 + HID)
#define SM_W2   (SM_B1 + HID)
#define SM_K    (SM_W2 + HID)
#define SM_D    (SM_K + 64)
#define SM_GRPBASE (SM_D + 64)               // 20736
// ---- per-group region ----
#define G_H1    0                            // [128][20]
#define G_E1    (G_H1 + HID*TP)              // 2560
#define G_F1    (G_E1 + HID*TP)              // 5120  h1'' then sbuf
#define G_AS    (G_F1 + HID*TP)              // 7680
#define G_X     (G_AS + HID*TP)              // 10240 2 x [16][17]
#define G_G     (G_X + 2*TBS*XP)             // 10784 [16][9]
#define G_HVP   (G_G + TBS*GBP)              // 10928 [8][20]
#define G_FO    (G_HVP + 8*HVPP)             // 11088 [16][9]
#define G_SIZE  (G_FO + TBS*GBP)             // 11232
#define SM_TOTAL (SM_GRPBASE + 3*G_SIZE)     // 54432 floats = 217728 B
#define SMEM_BYTES (SM_TOTAL * sizeof(float))

__device__ __forceinline__ ull pack2(float x, float y) {
    ull r; asm("mov.b64 %0, {%1,%2};" : "=l"(r) : "f"(x), "f"(y)); return r;
}
__device__ __forceinline__ float2 unpack2(ull v) {
    float2 r; asm("mov.b64 {%0,%1}, %2;" : "=f"(r.x), "=f"(r.y) : "l"(v)); return r;
}
__device__ __forceinline__ ull fma2(ull a, ull b, ull c) {
    ull r; asm("fma.rn.f32x2 %0, %1, %2, %3;" : "=l"(r) : "l"(a), "l"(b), "l"(c)); return r;
}
// fast tanh: 1 - 2/(e^{2z}+1). Correct saturation, rel err ~1e-6.
__device__ __forceinline__ float ftanh(float z) {
    float e = __expf(2.f * z);
    return 1.f - __fdividef(2.f, e + 1.f);
}

extern "C" __global__ void __launch_bounds__(NTHREADS, 1)
dyn_kernel(const float* __restrict__ X,  const float* __restrict__ Km,
           const float* __restrict__ Dm, const float* __restrict__ W0,
           const float* __restrict__ b0, const float* __restrict__ W1,
           const float* __restrict__ b1, const float* __restrict__ W2,
           float* __restrict__ out)
{
    extern __shared__ float sm[];
    float* W1s = sm + SM_W1;
    float* W0s = sm + SM_W0;
    float* W0d = sm + SM_W0D;
    float* b0s = sm + SM_B0;
    float* b1s = sm + SM_B1;
    float* w2s = sm + SM_W2;
    float* Ks  = sm + SM_K;
    float* Ds  = sm + SM_D;

    const int tid   = threadIdx.x;
    const int group = tid >> 8;          // 0,1,2
    const int gtid  = tid & 255;
    const int gbar  = group + 1;         // named barriers 1..3

    float* gbase = sm + SM_GRPBASE + group * G_SIZE;
    float* h1s = gbase + G_H1;
    float* e1s = gbase + G_E1;
    float* f1s = gbase + G_F1;
    float* a_s = gbase + G_AS;
    float* Xq  = gbase + G_X;
    float* gbf = gbase + G_G;
    float* hvp_s = gbase + G_HVP;
    float* fobuf = gbase + G_FO;

    // ---- one-time weight staging (whole CTA) ----
    for (int idx = tid; idx < HID*HID; idx += NTHREADS) {
        int j = idx >> 7, i = idx & 127;
        W1s[j*W1P + i] = W1[idx];
    }
    for (int idx = tid; idx < HID*DIMV; idx += NTHREADS) {
        int i = idx >> 3, k = idx & 7;
        float w = W0[idx];
        W0s[i*W0P + k] = w;
        W0d[idx*2]     = w;
        W0d[idx*2 + 1] = w;
    }
    if (tid < HID) { b0s[tid] = b0[tid]; b1s[tid] = b1[tid]; w2s[tid] = W2[tid]; }
    if (tid < 64)  { Ks[tid] = Km[tid]; Ds[tid] = Dm[tid]; }
    __syncthreads();

    const int tx = gtid & 3;            // 4 sample-groups x 4 samples
    const int jy = gtid >> 2;           // 64 groups x 2 rows/cols
    const int s0 = tx * 4;
    const int j0 = jy * 2;
    const int qf = gtid & 7;
    const int sf = gtid >> 3;           // 0..15 for gtid<128
    const int wrp = gtid >> 5;          // warp in group (0..7)

    const int worker = blockIdx.x * 3 + group;

    // X staging: 256 elements per tile, 1 per thread
    const int xoff = (gtid >> 4) * XP + (gtid & 15);

    // ---- prologue: stage X for first tile into buffer 0 ----
    Xq[xoff] = X[worker * (TBS*16) + gtid];
    asm volatile("bar.sync %0, 256;" :: "r"(gbar) : "memory");
    int xb = 0;

    for (int tile = worker; tile < NTILES; tile += NWORKERS) {
        const int base = tile * TBS;
        float* Xs = Xq + xb * (TBS * XP);

        // ---- prefetch next tile's X into a register ----
        const int nt = tile + NWORKERS;
        float xp0 = 0.f;
        if (nt < NTILES) xp0 = X[nt*(TBS*16) + gtid];

        // ---- phase 1: h1, h1', h1''  (2 rows x 4 samples) ----
        {
            float hh[2][4], ee[2][4], ff[2][4];
            #pragma unroll
            for (int ss = 0; ss < 4; ss++) {
                const int s = s0 + ss;
                float xr[8], vr[8];
                #pragma unroll
                for (int k = 0; k < 8; k++) { xr[k] = Xs[s*XP + k]; vr[k] = Xs[s*XP + 8 + k]; }
                #pragma unroll
                for (int c = 0; c < 2; c++) {
                    const int i = j0 + c;
                    float z = b0s[i], t = 0.f;
                    #pragma unroll
                    for (int k = 0; k < 8; k++) {
                        float w = W0s[i*W0P + k];
                        z = fmaf(w, xr[k], z);
                        t = fmaf(w, vr[k], t);
                    }
                    float h = ftanh(z);
                    float d = 1.f - h*h;
                    float e = d * t;
                    float f = -2.f * h * t * e;
                    hh[c][ss] = h; ee[c][ss] = e; ff[c][ss] = f;
                }
            }
            #pragma unroll
            for (int c = 0; c < 2; c++) {
                const int i = j0 + c;
                *(float4*)(h1s + i*TP + s0) = make_float4(hh[c][0],hh[c][1],hh[c][2],hh[c][3]);
                *(float4*)(e1s + i*TP + s0) = make_float4(ee[c][0],ee[c][1],ee[c][2],ee[c][3]);
                *(float4*)(f1s + i*TP + s0) = make_float4(ff[c][0],ff[c][1],ff[c][2],ff[c][3]);
            }
        }
        asm volatile("bar.sync %0, 256;" :: "r"(gbar) : "memory");   // B2: h/e/f ready

        // ---- store prefetched X into the other buffer ----
        if (nt < NTILES) {
            float* Xn = Xq + (xb ^ 1) * (TBS * XP);
            Xn[xoff] = xp0;
        }

        // ---- phase 2: z2 = W1 h1, P = W1 h1'  (2 rows x 4 samples, f32x2) ----
        ull az[2][2], ap[2][2];
        az[0][0]=0ull; az[0][1]=0ull; az[1][0]=0ull; az[1][1]=0ull;
        ap[0][0]=0ull; ap[0][1]=0ull; ap[1][0]=0ull; ap[1][1]=0ull;
        {
            const float* hp = h1s + s0;
            const float* ep = e1s + s0;
            #pragma unroll 2
            for (int i = 0; i < HID; i += 4) {
                const float4 wr0 = *(const float4*)(W1s + (j0+0)*W1P + i);
                const float4 wr1 = *(const float4*)(W1s + (j0+1)*W1P + i);
                const float* wa0 = (const float*)&wr0;
                const float* wa1 = (const float*)&wr1;
                #pragma unroll
                for (int ii = 0; ii < 4; ii++) {
                    const ulonglong2 hv = *(const ulonglong2*)(hp + (i+ii)*TP);
                    const ulonglong2 ev = *(const ulonglong2*)(ep + (i+ii)*TP);
                    ull w;
                    w = pack2(wa0[ii], wa0[ii]);
                    az[0][0]=fma2(w,hv.x,az[0][0]); az[0][1]=fma2(w,hv.y,az[0][1]);
                    ap[0][0]=fma2(w,ev.x,ap[0][0]); ap[0][1]=fma2(w,ev.y,ap[0][1]);
                    w = pack2(wa1[ii], wa1[ii]);
                    az[1][0]=fma2(w,hv.x,az[1][0]); az[1][1]=fma2(w,hv.y,az[1][1]);
                    ap[1][0]=fma2(w,ev.x,ap[1][0]); ap[1][1]=fma2(w,ev.y,ap[1][1]);
                }
            }
        }

        // ---- phase-2 epilogue (no barrier: own a_s rows only) ----
        float hvp[4] = {0.f, 0.f, 0.f, 0.f};
        #pragma unroll
        for (int c = 0; c < 2; c++) {
            const int j = j0 + c;
            const float2 z01 = unpack2(az[c][0]), z23 = unpack2(az[c][1]);
            const float2 p01 = unpack2(ap[c][0]), p23 = unpack2(ap[c][1]);
            const float zz[4] = {z01.x, z01.y, z23.x, z23.y};
            const float pp[4] = {p01.x, p01.y, p23.x, p23.y};
            const float w2j = w2s[j];
            const float bj  = b1s[j];
            float av[4];
            #pragma unroll
            for (int ss = 0; ss < 4; ss++) {
                float h2 = ftanh(zz[ss] + bj);
                float d2 = 1.f - h2*h2;
                float P = pp[ss];
                hvp[ss] = fmaf(-2.f*w2j, h2*d2*P*P, hvp[ss]);
                av[ss] = d2 * w2j;
            }
            *(float4*)(a_s + j*TP + s0) = make_float4(av[0],av[1],av[2],av[3]);
        }
        asm volatile("bar.sync %0, 256;" :: "r"(gbar) : "memory");   // B3: a ready

        // ---- phase 3: U = W1^T a  (2 cols x 4 samples, f32x2) ----
        ull au[2][2];
        au[0][0]=0ull; au[0][1]=0ull; au[1][0]=0ull; au[1][1]=0ull;
        {
            const float* apnt = a_s + s0;
            #pragma unroll 2
            for (int j = 0; j < HID; j++) {
                const ulonglong2 av = *(const ulonglong2*)(apnt + j*TP);
                const float2 wv = *(const float2*)(W1s + j*W1P + j0);
                ull w;
                w = pack2(wv.x, wv.x);
                au[0][0]=fma2(w,av.x,au[0][0]); au[0][1]=fma2(w,av.y,au[0][1]);
                w = pack2(wv.y, wv.y);
                au[1][0]=fma2(w,av.x,au[1][0]); au[1][1]=fma2(w,av.y,au[1][1]);
            }
        }

        // ---- phase-3 epilogue (own rows): hvv += U.h1''; sbuf(f1s) = d1*U ----
        #pragma unroll
        for (int c = 0; c < 2; c++) {
            const int i = j0 + c;
            const float2 u01 = unpack2(au[c][0]), u23 = unpack2(au[c][1]);
            const float uu[4] = {u01.x, u01.y, u23.x, u23.y};
            const float4 fv = *(const float4*)(f1s + i*TP + s0);
            const float4 hv = *(const float4*)(h1s + i*TP + s0);
            const float fpp[4] = {fv.x, fv.y, fv.z, fv.w};
            const float hh4[4] = {hv.x, hv.y, hv.z, hv.w};
            float sv[4];
            #pragma unroll
            for (int ss = 0; ss < 4; ss++) {
                hvp[ss] = fmaf(uu[ss], fpp[ss], hvp[ss]);
                sv[ss]  = (1.f - hh4[ss]*hh4[ss]) * uu[ss];
            }
            *(float4*)(f1s + i*TP + s0) = make_float4(sv[0],sv[1],sv[2],sv[3]);
        }
        // ---- warp-level hvv reduce over the warp's 8 jy groups ----
        #pragma unroll
        for (int ss = 0; ss < 4; ss++) {
            hvp[ss] += __shfl_xor_sync(0xffffffffu, hvp[ss], 4);
            hvp[ss] += __shfl_xor_sync(0xffffffffu, hvp[ss], 8);
            hvp[ss] += __shfl_xor_sync(0xffffffffu, hvp[ss], 16);
        }
        if ((gtid & 31) < 4)   // one lane per tx stores the warp partial
            *(float4*)(hvp_s + wrp*HVPP + s0) = make_float4(hvp[0],hvp[1],hvp[2],hvp[3]);
        asm volatile("bar.sync %0, 256;" :: "r"(gbar) : "memory");   // B4: sbuf+hvp ready

        // ---- phase 4: g = W0^T sbuf (threads 0-63) || force matvec (64-127) ----
        if (gtid < 64) {
            const int q  = gtid & 7;
            const int sp = gtid >> 3;          // 0..7 -> samples 2sp,2sp+1
            ull acc = 0ull;
            const ull* w0dp = (const ull*)(W0d) + q;
            const float* fp = f1s + 2*sp;
            #pragma unroll 4
            for (int i = 0; i < HID; i++)
                acc = fma2(w0dp[i*8], *(const ull*)(fp + i*TP), acc);
            float2 gv = unpack2(acc);
            gbf[(2*sp)*GBP + q]   = gv.x;
            gbf[(2*sp+1)*GBP + q] = gv.y;
        } else if (gtid < 128) {
            const int idx = gtid - 64;
            const int q  = idx & 7;
            const int sp = idx >> 3;           // 0..7
            #pragma unroll
            for (int u = 0; u < 2; u++) {
                const int s = 2*sp + u;
                float fo = 0.f;
                #pragma unroll
                for (int k = 0; k < 8; k++) {
                    fo = fmaf(-Ds[q*8+k], Xs[s*XP + 8 + k], fo);
                    fo = fmaf(-Ks[q*8+k], Xs[s*XP + k],     fo);
                }
                fobuf[s*GBP + q] = fo;
            }
        }
        asm volatile("bar.sync %0, 256;" :: "r"(gbar) : "memory");   // B5: gbf+fobuf ready

        // ---- phase 5 (threads 0-127): Sherman-Morrison combine + store ----
        if (gtid < 128) {
            float g[8], fo[8];
            #pragma unroll
            for (int k = 0; k < 8; k++) g[k]  = gbf[sf*GBP + k];
            #pragma unroll
            for (int k = 0; k < 8; k++) fo[k] = fobuf[sf*GBP + k];
            float gg = 0.f, gf = 0.f;
            #pragma unroll
            for (int k = 0; k < 8; k++) {
                gg = fmaf(g[k], g[k], gg);
                gf = fmaf(g[k], fo[k], gf);
            }
            float hvv = 0.f;
            #pragma unroll
            for (int w = 0; w < 8; w++) hvv += hvp_s[w*HVPP + sf];
            float scale = (gf + hvv) / (1.f + gg);
            out[(base + sf)*8 + qf] = fo[qf] - g[qf]*scale;
        }
        // no trailing barrier: next-tile hazards covered by B2..B5
        xb ^= 1;
    }
}

extern "C" void kernel_launch(void* const* d_in, const int* in_sizes, int n_in,
                              void* d_out, int out_size)
{
    const float* X  = (const float*)d_in[0];
    const float* Km = (const float*)d_in[1];
    const float* Dm = (const float*)d_in[2];
    const float* W0 = (const float*)d_in[3];
    const float* b0 = (const float*)d_in[4];
    const float* W1 = (const float*)d_in[5];
    const float* b1 = (const float*)d_in[6];
    const float* W2 = (const float*)d_in[7];

    cudaFuncSetAttribute(dyn_kernel, cudaFuncAttributeMaxDynamicSharedMemorySize,
                         (int)SMEM_BYTES);
    dyn_kernel<<<GRID, NTHREADS, SMEM_BYTES>>>(X, Km, Dm, W0, b0, W1, b1, W2,
                                               (float*)d_out);
}

// round 15
// speedup vs baseline: 1.4894x; 1.4894x over previous
#include <cuda_runtime.h>
#include <math.h>

// Dynamics_79843442033036 — fused analytic grad/HVV kernel.
// Round 15 = round-13 (best, 159.9us) + micro: phase-3 unroll 4,
// phase-4 unroll 8, __fdividef. r=ss=4 @512thr is the proven optimum of
// LDS/FLOP (1/r+1/ss) vs register cap; do not perturb.

typedef unsigned long long ull;

#define HID     128
#define DIMV    8
#define BATCHN  65536
#define TBS     32
#define NTILES  (BATCHN / TBS)      // 2048
#define NTHREADS 512
#define GTHREADS 256
#define GRID    152
#define NWORKERS (GRID * 2)

#define W1P 132
#define XP  17
#define W0P 10
#define HVP 33
#define GBP 9

// ---- shared weights (float offsets) ----
#define SM_W1   0                            // [128][132]
#define SM_W0   (SM_W1 + HID*W1P)            // 16896
#define SM_W0D  (SM_W0 + HID*W0P)            // 18176
#define SM_B0   (SM_W0D + HID*DIMV*2)        // 20224
#define SM_B1   (SM_B0 + HID)
#define SM_W2   (SM_B1 + HID)
#define SM_K    (SM_W2 + HID)
#define SM_D    (SM_K + 64)
#define SM_GRPBASE (SM_D + 64)               // 20736
// ---- per-group region ----
#define G_H1    0                            // [128][32]
#define G_E1    (G_H1 + HID*TBS)             // 4096
#define G_F1    (G_E1 + HID*TBS)             // 8192   h1'' then sbuf
#define G_AS    (G_F1 + HID*TBS)             // 12288  [128][32]
#define G_X     (G_AS + HID*TBS)             // 16384  2 x [32][17]
#define G_G     (G_X + 2*TBS*XP)             // 17472  [32][9]
#define G_HVP   (G_G + TBS*GBP)              // 17760  [8][33]
#define G_FO    (G_HVP + 8*HVP)              // 18024  [32][9] force buf
#define G_SIZE  (G_FO + TBS*GBP)             // 18312
#define SM_TOTAL (SM_GRPBASE + 2*G_SIZE)     // 57360 floats = 229440 B
#define SMEM_BYTES (SM_TOTAL * sizeof(float))

__device__ __forceinline__ ull pack2(float x, float y) {
    ull r; asm("mov.b64 %0, {%1,%2};" : "=l"(r) : "f"(x), "f"(y)); return r;
}
__device__ __forceinline__ float2 unpack2(ull v) {
    float2 r; asm("mov.b64 {%0,%1}, %2;" : "=f"(r.x), "=f"(r.y) : "l"(v)); return r;
}
__device__ __forceinline__ ull fma2(ull a, ull b, ull c) {
    ull r; asm("fma.rn.f32x2 %0, %1, %2, %3;" : "=l"(r) : "l"(a), "l"(b), "l"(c)); return r;
}
// fast tanh: 1 - 2/(e^{2z}+1). Correct saturation, rel err ~1e-6.
__device__ __forceinline__ float ftanh(float z) {
    float e = __expf(2.f * z);
    return 1.f - __fdividef(2.f, e + 1.f);
}

extern "C" __global__ void __launch_bounds__(NTHREADS, 1)
dyn_kernel(const float* __restrict__ X,  const float* __restrict__ Km,
           const float* __restrict__ Dm, const float* __restrict__ W0,
           const float* __restrict__ b0, const float* __restrict__ W1,
           const float* __restrict__ b1, const float* __restrict__ W2,
           float* __restrict__ out)
{
    extern __shared__ float sm[];
    float* W1s = sm + SM_W1;
    float* W0s = sm + SM_W0;
    float* W0d = sm + SM_W0D;
    float* b0s = sm + SM_B0;
    float* b1s = sm + SM_B1;
    float* w2s = sm + SM_W2;
    float* Ks  = sm + SM_K;
    float* Ds  = sm + SM_D;

    const int tid   = threadIdx.x;
    const int group = tid >> 8;
    const int gtid  = tid & 255;
    const int gbar  = group + 1;

    float* gbase = sm + SM_GRPBASE + group * G_SIZE;
    float* h1s = gbase + G_H1;
    float* e1s = gbase + G_E1;
    float* f1s = gbase + G_F1;
    float* a_s = gbase + G_AS;
    float* Xq  = gbase + G_X;
    float* gbf = gbase + G_G;
    float* hvp_s = gbase + G_HVP;
    float* fobuf = gbase + G_FO;

    // ---- one-time weight staging (whole CTA) ----
    for (int idx = tid; idx < HID*HID; idx += NTHREADS) {
        int j = idx >> 7, i = idx & 127;
        W1s[j*W1P + i] = W1[idx];
    }
    for (int idx = tid; idx < HID*DIMV; idx += NTHREADS) {
        int i = idx >> 3, k = idx & 7;
        float w = W0[idx];
        W0s[i*W0P + k] = w;
        W0d[idx*2]     = w;
        W0d[idx*2 + 1] = w;
    }
    if (tid < HID) { b0s[tid] = b0[tid]; b1s[tid] = b1[tid]; w2s[tid] = W2[tid]; }
    if (tid < 64)  { Ks[tid] = Km[tid]; Ds[tid] = Dm[tid]; }
    __syncthreads();

    const int tx = gtid & 7;            // 8 sample-groups x 4 samples
    const int jy = gtid >> 3;           // 32 hidden-groups x 4 rows
    const int s0 = tx * 4;
    const int j0 = jy * 4;
    const int qf = gtid & 7;
    const int sf = gtid >> 3;
    const int wrp = gtid >> 5;          // warp id in group (0..7)

    const int worker = blockIdx.x * 2 + group;

    // X staging offsets (each thread stages 2 elements)
    const int xoff0 = (gtid >> 4) * XP + (gtid & 15);
    const int xoff1 = xoff0 + 16 * XP;

    // ---- prologue: stage X for first tile into buffer 0 ----
    {
        const int b0i = worker * (TBS * 16);
        Xq[xoff0] = X[b0i + gtid];
        Xq[xoff1] = X[b0i + gtid + 256];
    }
    asm volatile("bar.sync %0, 256;" :: "r"(gbar) : "memory");
    int xb = 0;

    for (int tile = worker; tile < NTILES; tile += NWORKERS) {
        const int base = tile * TBS;
        float* Xs = Xq + xb * (TBS * XP);

        // ---- prefetch next tile's X into registers ----
        const int nt = tile + NWORKERS;
        float xp0 = 0.f, xp1 = 0.f;
        if (nt < NTILES) {
            xp0 = X[nt*512 + gtid];
            xp1 = X[nt*512 + gtid + 256];
        }

        // ---- phase 1: h1, h1', h1'' ----
        {
            float hh[4][4], ee[4][4], ff[4][4];   // [c][ss]
            #pragma unroll
            for (int ss = 0; ss < 4; ss++) {
                const int s = s0 + ss;
                float xr[8], vr[8];
                #pragma unroll
                for (int k = 0; k < 8; k++) { xr[k] = Xs[s*XP + k]; vr[k] = Xs[s*XP + 8 + k]; }
                #pragma unroll
                for (int c = 0; c < 4; c++) {
                    const int i = j0 + c;
                    float z = b0s[i], t = 0.f;
                    #pragma unroll
                    for (int k = 0; k < 8; k++) {
                        float w = W0s[i*W0P + k];
                        z = fmaf(w, xr[k], z);
                        t = fmaf(w, vr[k], t);
                    }
                    float h = ftanh(z);
                    float d = 1.f - h*h;
                    float e = d * t;
                    float f = -2.f * h * t * e;
                    hh[c][ss] = h; ee[c][ss] = e; ff[c][ss] = f;
                }
            }
            #pragma unroll
            for (int c = 0; c < 4; c++) {
                const int i = j0 + c;
                *(float4*)(h1s + i*TBS + s0) = make_float4(hh[c][0],hh[c][1],hh[c][2],hh[c][3]);
                *(float4*)(e1s + i*TBS + s0) = make_float4(ee[c][0],ee[c][1],ee[c][2],ee[c][3]);
                *(float4*)(f1s + i*TBS + s0) = make_float4(ff[c][0],ff[c][1],ff[c][2],ff[c][3]);
            }
        }
        asm volatile("bar.sync %0, 256;" :: "r"(gbar) : "memory");   // B2: h/e/f ready

        // ---- store prefetched X into the other buffer (prev reads done @ B2) ----
        if (nt < NTILES) {
            float* Xn = Xq + (xb ^ 1) * (TBS * XP);
            Xn[xoff0] = xp0;
            Xn[xoff1] = xp1;
        }

        // ---- phase 2: z2 = W1 h1, P = W1 h1' (f32x2, sample-packed) ----
        ull az2[4][2], ap2[4][2];
        #pragma unroll
        for (int c = 0; c < 4; c++) {
            az2[c][0]=0ull; az2[c][1]=0ull;
            ap2[c][0]=0ull; ap2[c][1]=0ull;
        }
        {
            const float* hp = h1s + s0;
            const float* ep = e1s + s0;
            #pragma unroll 2
            for (int i = 0; i < HID; i += 4) {
                const float4 wr0 = *(const float4*)(W1s + (j0+0)*W1P + i);
                const float4 wr1 = *(const float4*)(W1s + (j0+1)*W1P + i);
                const float4 wr2 = *(const float4*)(W1s + (j0+2)*W1P + i);
                const float4 wr3 = *(const float4*)(W1s + (j0+3)*W1P + i);
                const float* wa0 = (const float*)&wr0;
                const float* wa1 = (const float*)&wr1;
                const float* wa2 = (const float*)&wr2;
                const float* wa3 = (const float*)&wr3;
                #pragma unroll
                for (int ii = 0; ii < 4; ii++) {
                    const ulonglong2 hv = *(const ulonglong2*)(hp + (i+ii)*TBS);
                    const ulonglong2 ev = *(const ulonglong2*)(ep + (i+ii)*TBS);
                    ull w;
                    w = pack2(wa0[ii], wa0[ii]);
                    az2[0][0]=fma2(w,hv.x,az2[0][0]); az2[0][1]=fma2(w,hv.y,az2[0][1]);
                    ap2[0][0]=fma2(w,ev.x,ap2[0][0]); ap2[0][1]=fma2(w,ev.y,ap2[0][1]);
                    w = pack2(wa1[ii], wa1[ii]);
                    az2[1][0]=fma2(w,hv.x,az2[1][0]); az2[1][1]=fma2(w,hv.y,az2[1][1]);
                    ap2[1][0]=fma2(w,ev.x,ap2[1][0]); ap2[1][1]=fma2(w,ev.y,ap2[1][1]);
                    w = pack2(wa2[ii], wa2[ii]);
                    az2[2][0]=fma2(w,hv.x,az2[2][0]); az2[2][1]=fma2(w,hv.y,az2[2][1]);
                    ap2[2][0]=fma2(w,ev.x,ap2[2][0]); ap2[2][1]=fma2(w,ev.y,ap2[2][1]);
                    w = pack2(wa3[ii], wa3[ii]);
                    az2[3][0]=fma2(w,hv.x,az2[3][0]); az2[3][1]=fma2(w,hv.y,az2[3][1]);
                    ap2[3][0]=fma2(w,ev.x,ap2[3][0]); ap2[3][1]=fma2(w,ev.y,ap2[3][1]);
                }
            }
        }

        // ---- phase-2 epilogue (no barrier: a_s own rows only) ----
        float hvp[4] = {0.f, 0.f, 0.f, 0.f};
        #pragma unroll
        for (int c = 0; c < 4; c++) {
            const int j = j0 + c;
            const float2 z01 = unpack2(az2[c][0]), z23 = unpack2(az2[c][1]);
            const float2 p01 = unpack2(ap2[c][0]), p23 = unpack2(ap2[c][1]);
            const float zz[4] = {z01.x, z01.y, z23.x, z23.y};
            const float pp[4] = {p01.x, p01.y, p23.x, p23.y};
            const float w2j = w2s[j];
            const float bj  = b1s[j];
            float av[4];
            #pragma unroll
            for (int ss = 0; ss < 4; ss++) {
                float h2 = ftanh(zz[ss] + bj);
                float d2 = 1.f - h2*h2;
                float P = pp[ss];
                hvp[ss] = fmaf(-2.f*w2j, h2*d2*P*P, hvp[ss]);
                av[ss] = d2 * w2j;
            }
            *(float4*)(a_s + j*TBS + s0) = make_float4(av[0],av[1],av[2],av[3]);
        }
        asm volatile("bar.sync %0, 256;" :: "r"(gbar) : "memory");   // B3: a ready

        // ---- phase 3: U = W1^T a (f32x2) ----
        ull au2[4][2];
        #pragma unroll
        for (int c = 0; c < 4; c++) { au2[c][0]=0ull; au2[c][1]=0ull; }
        {
            const float* apnt = a_s + s0;
            #pragma unroll 4
            for (int j = 0; j < HID; j++) {
                const ulonglong2 av = *(const ulonglong2*)(apnt + j*TBS);
                const float4 wv = *(const float4*)(W1s + j*W1P + j0);
                const float* wa = (const float*)&wv;
                ull w;
                w = pack2(wa[0], wa[0]);
                au2[0][0]=fma2(w,av.x,au2[0][0]); au2[0][1]=fma2(w,av.y,au2[0][1]);
                w = pack2(wa[1], wa[1]);
                au2[1][0]=fma2(w,av.x,au2[1][0]); au2[1][1]=fma2(w,av.y,au2[1][1]);
                w = pack2(wa[2], wa[2]);
                au2[2][0]=fma2(w,av.x,au2[2][0]); au2[2][1]=fma2(w,av.y,au2[2][1]);
                w = pack2(wa[3], wa[3]);
                au2[3][0]=fma2(w,av.x,au2[3][0]); au2[3][1]=fma2(w,av.y,au2[3][1]);
            }
        }

        // ---- phase-3 epilogue (own rows): hvv += U.h1''; sbuf(f1s) = d1*U ----
        #pragma unroll
        for (int c = 0; c < 4; c++) {
            const int i = j0 + c;
            const float2 u01 = unpack2(au2[c][0]), u23 = unpack2(au2[c][1]);
            const float uu[4] = {u01.x, u01.y, u23.x, u23.y};
            const float4 fv = *(const float4*)(f1s + i*TBS + s0);
            const float4 hv = *(const float4*)(h1s + i*TBS + s0);
            const float fpp[4] = {fv.x, fv.y, fv.z, fv.w};
            const float hh4[4] = {hv.x, hv.y, hv.z, hv.w};
            float sv[4];
            #pragma unroll
            for (int ss = 0; ss < 4; ss++) {
                hvp[ss] = fmaf(uu[ss], fpp[ss], hvp[ss]);
                sv[ss]  = (1.f - hh4[ss]*hh4[ss]) * uu[ss];
            }
            *(float4*)(f1s + i*TBS + s0) = make_float4(sv[0],sv[1],sv[2],sv[3]);
        }
        // ---- warp-level hvv partial reduce over the warp's 4 jy groups ----
        #pragma unroll
        for (int ss = 0; ss < 4; ss++) {
            hvp[ss] += __shfl_xor_sync(0xffffffffu, hvp[ss], 8);
            hvp[ss] += __shfl_xor_sync(0xffffffffu, hvp[ss], 16);
        }
        if ((gtid & 31) < 8) {   // one lane per tx stores the warp partial
            #pragma unroll
            for (int ss = 0; ss < 4; ss++)
                hvp_s[wrp*HVP + s0 + ss] = hvp[ss];
        }
        asm volatile("bar.sync %0, 256;" :: "r"(gbar) : "memory");   // B4: sbuf+hvp ready

        // ---- phase 4 (warps 0-3): g = W0^T sbuf  ||  (warps 4-7): force matvec ----
        if (gtid < 128) {
            const int q  = gtid & 7;
            const int sp = gtid >> 3;
            ull acc = 0ull;
            const ull* w0dp = (const ull*)(W0d) + q;
            const float* fp = f1s + 2*sp;
            #pragma unroll 8
            for (int i = 0; i < HID; i++)
                acc = fma2(w0dp[i*8], *(const ull*)(fp + i*TBS), acc);
            float2 gv = unpack2(acc);
            gbf[(2*sp)*GBP + q]   = gv.x;
            gbf[(2*sp+1)*GBP + q] = gv.y;
        } else {
            // force: fo[q][s] = -(D[q,:].v + K[q,:].x), 2 samples per thread
            const int idx = gtid - 128;
            const int q  = idx & 7;
            const int sp = idx >> 3;           // 0..15
            #pragma unroll
            for (int u = 0; u < 2; u++) {
                const int s = 2*sp + u;
                float fo = 0.f;
                #pragma unroll
                for (int k = 0; k < 8; k++) {
                    fo = fmaf(-Ds[q*8+k], Xs[s*XP + 8 + k], fo);
                    fo = fmaf(-Ks[q*8+k], Xs[s*XP + k],     fo);
                }
                fobuf[s*GBP + q] = fo;
            }
        }
        asm volatile("bar.sync %0, 256;" :: "r"(gbar) : "memory");   // B5: gbf+fobuf ready

        // ---- phase 5: Sherman-Morrison combine + coalesced store ----
        {
            float g[8], fo[8];
            #pragma unroll
            for (int k = 0; k < 8; k++) g[k]  = gbf[sf*GBP + k];
            #pragma unroll
            for (int k = 0; k < 8; k++) fo[k] = fobuf[sf*GBP + k];
            float gg = 0.f, gf = 0.f;
            #pragma unroll
            for (int k = 0; k < 8; k++) {
                gg = fmaf(g[k], g[k], gg);
                gf = fmaf(g[k], fo[k], gf);
            }
            float hvv = 0.f;
            #pragma unroll
            for (int w = 0; w < 8; w++) hvv += hvp_s[w*HVP + sf];
            float scale = __fdividef(gf + hvv, 1.f + gg);
            out[(base + sf)*8 + qf] = fo[qf] - g[qf]*scale;
        }
        // no trailing barrier: all next-tile hazards covered by B2/B3/B4/B5
        xb ^= 1;
    }
}

extern "C" void kernel_launch(void* const* d_in, const int* in_sizes, int n_in,
                              void* d_out, int out_size)
{
    const float* X  = (const float*)d_in[0];
    const float* Km = (const float*)d_in[1];
    const float* Dm = (const float*)d_in[2];
    const float* W0 = (const float*)d_in[3];
    const float* b0 = (const float*)d_in[4];
    const float* W1 = (const float*)d_in[5];
    const float* b1 = (const float*)d_in[6];
    const float* W2 = (const float*)d_in[7];

    cudaFuncSetAttribute(dyn_kernel, cudaFuncAttributeMaxDynamicSharedMemorySize,
                         (int)SMEM_BYTES);
    dyn_kernel<<<GRID, NTHREADS, SMEM_BYTES>>>(X, Km, Dm, W0, b0, W1, b1, W2,
                                               (float*)d_out);
}

// round 16
// speedup vs baseline: 1.4924x; 1.0020x over previous
#include <cuda_runtime.h>
#include <math.h>

// Dynamics_79843442033036 — fused analytic grad/HVV kernel.
// Round 15 = round-13 (best, 159.9us) + micro: phase-3 unroll 4,
// phase-4 unroll 8, __fdividef. r=ss=4 @512thr is the proven optimum of
// LDS/FLOP (1/r+1/ss) vs register cap; do not perturb.

typedef unsigned long long ull;

#define HID     128
#define DIMV    8
#define BATCHN  65536
#define TBS     32
#define NTILES  (BATCHN / TBS)      // 2048
#define NTHREADS 512
#define GTHREADS 256
#define GRID    152
#define NWORKERS (GRID * 2)

#define W1P 132
#define XP  17
#define W0P 10
#define HVP 33
#define GBP 9

// ---- shared weights (float offsets) ----
#define SM_W1   0                            // [128][132]
#define SM_W0   (SM_W1 + HID*W1P)            // 16896
#define SM_W0D  (SM_W0 + HID*W0P)            // 18176
#define SM_B0   (SM_W0D + HID*DIMV*2)        // 20224
#define SM_B1   (SM_B0 + HID)
#define SM_W2   (SM_B1 + HID)
#define SM_K    (SM_W2 + HID)
#define SM_D    (SM_K + 64)
#define SM_GRPBASE (SM_D + 64)               // 20736
// ---- per-group region ----
#define G_H1    0                            // [128][32]
#define G_E1    (G_H1 + HID*TBS)             // 4096
#define G_F1    (G_E1 + HID*TBS)             // 8192   h1'' then sbuf
#define G_AS    (G_F1 + HID*TBS)             // 12288  [128][32]
#define G_X     (G_AS + HID*TBS)             // 16384  2 x [32][17]
#define G_G     (G_X + 2*TBS*XP)             // 17472  [32][9]
#define G_HVP   (G_G + TBS*GBP)              // 17760  [8][33]
#define G_FO    (G_HVP + 8*HVP)              // 18024  [32][9] force buf
#define G_SIZE  (G_FO + TBS*GBP)             // 18312
#define SM_TOTAL (SM_GRPBASE + 2*G_SIZE)     // 57360 floats = 229440 B
#define SMEM_BYTES (SM_TOTAL * sizeof(float))

__device__ __forceinline__ ull pack2(float x, float y) {
    ull r; asm("mov.b64 %0, {%1,%2};" : "=l"(r) : "f"(x), "f"(y)); return r;
}
__device__ __forceinline__ float2 unpack2(ull v) {
    float2 r; asm("mov.b64 {%0,%1}, %2;" : "=f"(r.x), "=f"(r.y) : "l"(v)); return r;
}
__device__ __forceinline__ ull fma2(ull a, ull b, ull c) {
    ull r; asm("fma.rn.f32x2 %0, %1, %2, %3;" : "=l"(r) : "l"(a), "l"(b), "l"(c)); return r;
}
// fast tanh: 1 - 2/(e^{2z}+1). Correct saturation, rel err ~1e-6.
__device__ __forceinline__ float ftanh(float z) {
    float e = __expf(2.f * z);
    return 1.f - __fdividef(2.f, e + 1.f);
}

extern "C" __global__ void __launch_bounds__(NTHREADS, 1)
dyn_kernel(const float* __restrict__ X,  const float* __restrict__ Km,
           const float* __restrict__ Dm, const float* __restrict__ W0,
           const float* __restrict__ b0, const float* __restrict__ W1,
           const float* __restrict__ b1, const float* __restrict__ W2,
           float* __restrict__ out)
{
    extern __shared__ float sm[];
    float* W1s = sm + SM_W1;
    float* W0s = sm + SM_W0;
    float* W0d = sm + SM_W0D;
    float* b0s = sm + SM_B0;
    float* b1s = sm + SM_B1;
    float* w2s = sm + SM_W2;
    float* Ks  = sm + SM_K;
    float* Ds  = sm + SM_D;

    const int tid   = threadIdx.x;
    const int group = tid >> 8;
    const int gtid  = tid & 255;
    const int gbar  = group + 1;

    float* gbase = sm + SM_GRPBASE + group * G_SIZE;
    float* h1s = gbase + G_H1;
    float* e1s = gbase + G_E1;
    float* f1s = gbase + G_F1;
    float* a_s = gbase + G_AS;
    float* Xq  = gbase + G_X;
    float* gbf = gbase + G_G;
    float* hvp_s = gbase + G_HVP;
    float* fobuf = gbase + G_FO;

    // ---- one-time weight staging (whole CTA) ----
    for (int idx = tid; idx < HID*HID; idx += NTHREADS) {
        int j = idx >> 7, i = idx & 127;
        W1s[j*W1P + i] = W1[idx];
    }
    for (int idx = tid; idx < HID*DIMV; idx += NTHREADS) {
        int i = idx >> 3, k = idx & 7;
        float w = W0[idx];
        W0s[i*W0P + k] = w;
        W0d[idx*2]     = w;
        W0d[idx*2 + 1] = w;
    }
    if (tid < HID) { b0s[tid] = b0[tid]; b1s[tid] = b1[tid]; w2s[tid] = W2[tid]; }
    if (tid < 64)  { Ks[tid] = Km[tid]; Ds[tid] = Dm[tid]; }
    __syncthreads();

    const int tx = gtid & 7;            // 8 sample-groups x 4 samples
    const int jy = gtid >> 3;           // 32 hidden-groups x 4 rows
    const int s0 = tx * 4;
    const int j0 = jy * 4;
    const int qf = gtid & 7;
    const int sf = gtid >> 3;
    const int wrp = gtid >> 5;          // warp id in group (0..7)

    const int worker = blockIdx.x * 2 + group;

    // X staging offsets (each thread stages 2 elements)
    const int xoff0 = (gtid >> 4) * XP + (gtid & 15);
    const int xoff1 = xoff0 + 16 * XP;

    // ---- prologue: stage X for first tile into buffer 0 ----
    {
        const int b0i = worker * (TBS * 16);
        Xq[xoff0] = X[b0i + gtid];
        Xq[xoff1] = X[b0i + gtid + 256];
    }
    asm volatile("bar.sync %0, 256;" :: "r"(gbar) : "memory");
    int xb = 0;

    for (int tile = worker; tile < NTILES; tile += NWORKERS) {
        const int base = tile * TBS;
        float* Xs = Xq + xb * (TBS * XP);

        // ---- prefetch next tile's X into registers ----
        const int nt = tile + NWORKERS;
        float xp0 = 0.f, xp1 = 0.f;
        if (nt < NTILES) {
            xp0 = X[nt*512 + gtid];
            xp1 = X[nt*512 + gtid + 256];
        }

        // ---- phase 1: h1, h1', h1'' ----
        {
            float hh[4][4], ee[4][4], ff[4][4];   // [c][ss]
            #pragma unroll
            for (int ss = 0; ss < 4; ss++) {
                const int s = s0 + ss;
                float xr[8], vr[8];
                #pragma unroll
                for (int k = 0; k < 8; k++) { xr[k] = Xs[s*XP + k]; vr[k] = Xs[s*XP + 8 + k]; }
                #pragma unroll
                for (int c = 0; c < 4; c++) {
                    const int i = j0 + c;
                    float z = b0s[i], t = 0.f;
                    #pragma unroll
                    for (int k = 0; k < 8; k++) {
                        float w = W0s[i*W0P + k];
                        z = fmaf(w, xr[k], z);
                        t = fmaf(w, vr[k], t);
                    }
                    float h = ftanh(z);
                    float d = 1.f - h*h;
                    float e = d * t;
                    float f = -2.f * h * t * e;
                    hh[c][ss] = h; ee[c][ss] = e; ff[c][ss] = f;
                }
            }
            #pragma unroll
            for (int c = 0; c < 4; c++) {
                const int i = j0 + c;
                *(float4*)(h1s + i*TBS + s0) = make_float4(hh[c][0],hh[c][1],hh[c][2],hh[c][3]);
                *(float4*)(e1s + i*TBS + s0) = make_float4(ee[c][0],ee[c][1],ee[c][2],ee[c][3]);
                *(float4*)(f1s + i*TBS + s0) = make_float4(ff[c][0],ff[c][1],ff[c][2],ff[c][3]);
            }
        }
        asm volatile("bar.sync %0, 256;" :: "r"(gbar) : "memory");   // B2: h/e/f ready

        // ---- store prefetched X into the other buffer (prev reads done @ B2) ----
        if (nt < NTILES) {
            float* Xn = Xq + (xb ^ 1) * (TBS * XP);
            Xn[xoff0] = xp0;
            Xn[xoff1] = xp1;
        }

        // ---- phase 2: z2 = W1 h1, P = W1 h1' (f32x2, sample-packed) ----
        ull az2[4][2], ap2[4][2];
        #pragma unroll
        for (int c = 0; c < 4; c++) {
            az2[c][0]=0ull; az2[c][1]=0ull;
            ap2[c][0]=0ull; ap2[c][1]=0ull;
        }
        {
            const float* hp = h1s + s0;
            const float* ep = e1s + s0;
            #pragma unroll 2
            for (int i = 0; i < HID; i += 4) {
                const float4 wr0 = *(const float4*)(W1s + (j0+0)*W1P + i);
                const float4 wr1 = *(const float4*)(W1s + (j0+1)*W1P + i);
                const float4 wr2 = *(const float4*)(W1s + (j0+2)*W1P + i);
                const float4 wr3 = *(const float4*)(W1s + (j0+3)*W1P + i);
                const float* wa0 = (const float*)&wr0;
                const float* wa1 = (const float*)&wr1;
                const float* wa2 = (const float*)&wr2;
                const float* wa3 = (const float*)&wr3;
                #pragma unroll
                for (int ii = 0; ii < 4; ii++) {
                    const ulonglong2 hv = *(const ulonglong2*)(hp + (i+ii)*TBS);
                    const ulonglong2 ev = *(const ulonglong2*)(ep + (i+ii)*TBS);
                    ull w;
                    w = pack2(wa0[ii], wa0[ii]);
                    az2[0][0]=fma2(w,hv.x,az2[0][0]); az2[0][1]=fma2(w,hv.y,az2[0][1]);
                    ap2[0][0]=fma2(w,ev.x,ap2[0][0]); ap2[0][1]=fma2(w,ev.y,ap2[0][1]);
                    w = pack2(wa1[ii], wa1[ii]);
                    az2[1][0]=fma2(w,hv.x,az2[1][0]); az2[1][1]=fma2(w,hv.y,az2[1][1]);
                    ap2[1][0]=fma2(w,ev.x,ap2[1][0]); ap2[1][1]=fma2(w,ev.y,ap2[1][1]);
                    w = pack2(wa2[ii], wa2[ii]);
                    az2[2][0]=fma2(w,hv.x,az2[2][0]); az2[2][1]=fma2(w,hv.y,az2[2][1]);
                    ap2[2][0]=fma2(w,ev.x,ap2[2][0]); ap2[2][1]=fma2(w,ev.y,ap2[2][1]);
                    w = pack2(wa3[ii], wa3[ii]);
                    az2[3][0]=fma2(w,hv.x,az2[3][0]); az2[3][1]=fma2(w,hv.y,az2[3][1]);
                    ap2[3][0]=fma2(w,ev.x,ap2[3][0]); ap2[3][1]=fma2(w,ev.y,ap2[3][1]);
                }
            }
        }

        // ---- phase-2 epilogue (no barrier: a_s own rows only) ----
        float hvp[4] = {0.f, 0.f, 0.f, 0.f};
        #pragma unroll
        for (int c = 0; c < 4; c++) {
            const int j = j0 + c;
            const float2 z01 = unpack2(az2[c][0]), z23 = unpack2(az2[c][1]);
            const float2 p01 = unpack2(ap2[c][0]), p23 = unpack2(ap2[c][1]);
            const float zz[4] = {z01.x, z01.y, z23.x, z23.y};
            const float pp[4] = {p01.x, p01.y, p23.x, p23.y};
            const float w2j = w2s[j];
            const float bj  = b1s[j];
            float av[4];
            #pragma unroll
            for (int ss = 0; ss < 4; ss++) {
                float h2 = ftanh(zz[ss] + bj);
                float d2 = 1.f - h2*h2;
                float P = pp[ss];
                hvp[ss] = fmaf(-2.f*w2j, h2*d2*P*P, hvp[ss]);
                av[ss] = d2 * w2j;
            }
            *(float4*)(a_s + j*TBS + s0) = make_float4(av[0],av[1],av[2],av[3]);
        }
        asm volatile("bar.sync %0, 256;" :: "r"(gbar) : "memory");   // B3: a ready

        // ---- phase 3: U = W1^T a (f32x2) ----
        ull au2[4][2];
        #pragma unroll
        for (int c = 0; c < 4; c++) { au2[c][0]=0ull; au2[c][1]=0ull; }
        {
            const float* apnt = a_s + s0;
            #pragma unroll 4
            for (int j = 0; j < HID; j++) {
                const ulonglong2 av = *(const ulonglong2*)(apnt + j*TBS);
                const float4 wv = *(const float4*)(W1s + j*W1P + j0);
                const float* wa = (const float*)&wv;
                ull w;
                w = pack2(wa[0], wa[0]);
                au2[0][0]=fma2(w,av.x,au2[0][0]); au2[0][1]=fma2(w,av.y,au2[0][1]);
                w = pack2(wa[1], wa[1]);
                au2[1][0]=fma2(w,av.x,au2[1][0]); au2[1][1]=fma2(w,av.y,au2[1][1]);
                w = pack2(wa[2], wa[2]);
                au2[2][0]=fma2(w,av.x,au2[2][0]); au2[2][1]=fma2(w,av.y,au2[2][1]);
                w = pack2(wa[3], wa[3]);
                au2[3][0]=fma2(w,av.x,au2[3][0]); au2[3][1]=fma2(w,av.y,au2[3][1]);
            }
        }

        // ---- phase-3 epilogue (own rows): hvv += U.h1''; sbuf(f1s) = d1*U ----
        #pragma unroll
        for (int c = 0; c < 4; c++) {
            const int i = j0 + c;
            const float2 u01 = unpack2(au2[c][0]), u23 = unpack2(au2[c][1]);
            const float uu[4] = {u01.x, u01.y, u23.x, u23.y};
            const float4 fv = *(const float4*)(f1s + i*TBS + s0);
            const float4 hv = *(const float4*)(h1s + i*TBS + s0);
            const float fpp[4] = {fv.x, fv.y, fv.z, fv.w};
            const float hh4[4] = {hv.x, hv.y, hv.z, hv.w};
            float sv[4];
            #pragma unroll
            for (int ss = 0; ss < 4; ss++) {
                hvp[ss] = fmaf(uu[ss], fpp[ss], hvp[ss]);
                sv[ss]  = (1.f - hh4[ss]*hh4[ss]) * uu[ss];
            }
            *(float4*)(f1s + i*TBS + s0) = make_float4(sv[0],sv[1],sv[2],sv[3]);
        }
        // ---- warp-level hvv partial reduce over the warp's 4 jy groups ----
        #pragma unroll
        for (int ss = 0; ss < 4; ss++) {
            hvp[ss] += __shfl_xor_sync(0xffffffffu, hvp[ss], 8);
            hvp[ss] += __shfl_xor_sync(0xffffffffu, hvp[ss], 16);
        }
        if ((gtid & 31) < 8) {   // one lane per tx stores the warp partial
            #pragma unroll
            for (int ss = 0; ss < 4; ss++)
                hvp_s[wrp*HVP + s0 + ss] = hvp[ss];
        }
        asm volatile("bar.sync %0, 256;" :: "r"(gbar) : "memory");   // B4: sbuf+hvp ready

        // ---- phase 4 (warps 0-3): g = W0^T sbuf  ||  (warps 4-7): force matvec ----
        if (gtid < 128) {
            const int q  = gtid & 7;
            const int sp = gtid >> 3;
            ull acc = 0ull;
            const ull* w0dp = (const ull*)(W0d) + q;
            const float* fp = f1s + 2*sp;
            #pragma unroll 8
            for (int i = 0; i < HID; i++)
                acc = fma2(w0dp[i*8], *(const ull*)(fp + i*TBS), acc);
            float2 gv = unpack2(acc);
            gbf[(2*sp)*GBP + q]   = gv.x;
            gbf[(2*sp+1)*GBP + q] = gv.y;
        } else {
            // force: fo[q][s] = -(D[q,:].v + K[q,:].x), 2 samples per thread
            const int idx = gtid - 128;
            const int q  = idx & 7;
            const int sp = idx >> 3;           // 0..15
            #pragma unroll
            for (int u = 0; u < 2; u++) {
                const int s = 2*sp + u;
                float fo = 0.f;
                #pragma unroll
                for (int k = 0; k < 8; k++) {
                    fo = fmaf(-Ds[q*8+k], Xs[s*XP + 8 + k], fo);
                    fo = fmaf(-Ks[q*8+k], Xs[s*XP + k],     fo);
                }
                fobuf[s*GBP + q] = fo;
            }
        }
        asm volatile("bar.sync %0, 256;" :: "r"(gbar) : "memory");   // B5: gbf+fobuf ready

        // ---- phase 5: Sherman-Morrison combine + coalesced store ----
        {
            float g[8], fo[8];
            #pragma unroll
            for (int k = 0; k < 8; k++) g[k]  = gbf[sf*GBP + k];
            #pragma unroll
            for (int k = 0; k < 8; k++) fo[k] = fobuf[sf*GBP + k];
            float gg = 0.f, gf = 0.f;
            #pragma unroll
            for (int k = 0; k < 8; k++) {
                gg = fmaf(g[k], g[k], gg);
                gf = fmaf(g[k], fo[k], gf);
            }
            float hvv = 0.f;
            #pragma unroll
            for (int w = 0; w < 8; w++) hvv += hvp_s[w*HVP + sf];
            float scale = __fdividef(gf + hvv, 1.f + gg);
            out[(base + sf)*8 + qf] = fo[qf] - g[qf]*scale;
        }
        // no trailing barrier: all next-tile hazards covered by B2/B3/B4/B5
        xb ^= 1;
    }
}

extern "C" void kernel_launch(void* const* d_in, const int* in_sizes, int n_in,
                              void* d_out, int out_size)
{
    const float* X  = (const float*)d_in[0];
    const float* Km = (const float*)d_in[1];
    const float* Dm = (const float*)d_in[2];
    const float* W0 = (const float*)d_in[3];
    const float* b0 = (const float*)d_in[4];
    const float* W1 = (const float*)d_in[5];
    const float* b1 = (const float*)d_in[6];
    const float* W2 = (const float*)d_in[7];

    cudaFuncSetAttribute(dyn_kernel, cudaFuncAttributeMaxDynamicSharedMemorySize,
                         (int)SMEM_BYTES);
    dyn_kernel<<<GRID, NTHREADS, SMEM_BYTES>>>(X, Km, Dm, W0, b0, W1, b1, W2,
                                               (float*)d_out);
}